// round 16
// baseline (speedup 1.0000x reference)
#include <cuda_runtime.h>
#include <cuda_bf16.h>
#include <math.h>
#include <cstdint>

// Problem constants
#define Bz 32
#define Dd 128
#define Tt 2048
#define Kk 2048
#define Nn 65536   // Bz*Tt

// Output layout (concatenated reference tuple, all float32)
#define OFF_ZVQ     0
#define OFF_LOSS    8388608
#define OFF_EMBNEW  8388609
#define OFF_EMBSUM  8650753
#define OFF_ELEM    8912897
#define OFF_ENT     8914945
#define OFF_DK      8914946

#define MARG 0.40f
#define DOFF 1024.0f
#define CAP  3072

__device__ __constant__ float MUf  = 0.99f;
__device__ __constant__ float C1f  = (float)(1.0 - 0.99);

// Scratch (device globals; no allocation allowed)
__device__ int    g_cnt[Kk];
__device__ float  g_en2[Kk];
__device__ double g_loss;
__device__ double g_dk2;
__device__ uint4  g_ehi4[Kk * 16];            // [code][128 bf16] hi
__device__ unsigned long long g_best[Nn];     // packed (distbits<<11 | code)
__device__ int2   g_slab[512 * CAP];          // candidate (row, code) per pass1-CTA
__device__ int    g_scnt[512];
__device__ int    g_nff;
__device__ int    g_ffn[Nn];
__device__ int    g_done;
__device__ float4 g_sum4[Kk * Dd / 4];        // 16B-aligned EMA-sum accumulator

// ---------------------------------------------------------------------------
// Generic-PTX helpers (valid on compute_103)
// ---------------------------------------------------------------------------
__device__ __forceinline__ uint32_t smem_to_u32(const void* p) {
    uint32_t a;
    asm("{ .reg .u64 t; cvta.to.shared.u64 t, %1; cvt.u32.u64 %0, t; }" : "=r"(a) : "l"(p));
    return a;
}
#define LDSM4(r0, r1, r2, r3, addr) \
    asm volatile("ldmatrix.sync.aligned.m8n8.x4.shared.b16 {%0,%1,%2,%3}, [%4];" \
                 : "=r"(r0), "=r"(r1), "=r"(r2), "=r"(r3) : "r"(addr))
#define HMMA(c, a, b0, b1) \
    asm volatile("mma.sync.aligned.m16n8k16.row.col.f32.bf16.bf16.f32 " \
                 "{%0,%1,%2,%3}, {%4,%5,%6,%7}, {%8,%9}, {%0,%1,%2,%3};" \
                 : "+f"((c)[0]), "+f"((c)[1]), "+f"((c)[2]), "+f"((c)[3]) \
                 : "r"((a)[0]), "r"((a)[1]), "r"((a)[2]), "r"((a)[3]), "r"(b0), "r"(b1))
#define CP_ASYNC16(dst, src) \
    asm volatile("cp.async.cg.shared.global [%0], [%1], 16;" :: "r"(dst), "l"(src))
#define CP_COMMIT() asm volatile("cp.async.commit_group;" ::: "memory")
#define CP_WAIT1()  asm volatile("cp.async.wait_group 1;" ::: "memory")
#define CP_WAIT0()  asm volatile("cp.async.wait_group 0;" ::: "memory")
#define REDV4(ptr, a, b, c, d) \
    asm volatile("red.global.add.v4.f32 [%0], {%1, %2, %3, %4};" \
                 :: "l"(ptr), "f"(a), "f"(b), "f"(c), "f"(d) : "memory")

// ---------------------------------------------------------------------------
// K0: fused prep — one warp per code. float4 reads, packed bf16x2 stores.
// ---------------------------------------------------------------------------
__global__ __launch_bounds__(32)
void k_prep(const float* __restrict__ emb, const float* __restrict__ emb_sum) {
    int k = blockIdx.x, lane = threadIdx.x;
    int i4 = k * 32 + lane;
    float4 e = reinterpret_cast<const float4*>(emb)[i4];
    float4 s4 = reinterpret_cast<const float4*>(emb_sum)[i4];

    // bf16 convert, packed 8B store
    __nv_bfloat162 h01 = {__float2bfloat16(e.x), __float2bfloat16(e.y)};
    __nv_bfloat162 h23 = {__float2bfloat16(e.z), __float2bfloat16(e.w)};
    uint2 hp;
    hp.x = *reinterpret_cast<uint32_t*>(&h01);
    hp.y = *reinterpret_cast<uint32_t*>(&h23);
    reinterpret_cast<uint2*>(g_ehi4)[i4] = hp;

    g_sum4[i4] = make_float4(__fmul_rn(MUf, s4.x), __fmul_rn(MUf, s4.y),
                             __fmul_rn(MUf, s4.z), __fmul_rn(MUf, s4.w));

    float sq = e.x * e.x + e.y * e.y + e.z * e.z + e.w * e.w;
    #pragma unroll
    for (int o = 16; o > 0; o >>= 1) sq += __shfl_down_sync(0xffffffffu, sq, o);
    if (lane == 0) { g_en2[k] = sq; g_cnt[k] = 0; }
    g_best[k * 32 + lane] = ~0ull;
    if (k == 0 && lane == 1) { g_loss = 0.0; g_dk2 = 0.0; g_nff = 0; g_done = 0; }
}

// ---------------------------------------------------------------------------
// K1 (pass 1): mma.sync bf16, single-term zhi*ehi filter. (R12/R15 proven
// barrier structure; phase-A atomicMin diluted via quad shfl-min.)
// ---------------------------------------------------------------------------
#define ATC 512
#define RS2 272
#define ZHI 0
#define EBUF 34816
#define EBUFSZ 34816
#define SMIN (EBUF + 2 * EBUFSZ)
#define SCNT (SMIN + 512)
#define ASM_SMEM (SCNT + 16)

__global__ __launch_bounds__(ATC, 2)
void k_assign_mma(const float* __restrict__ z)
{
    extern __shared__ char smem[];
    const uint32_t sbase = smem_to_u32(smem);
    int*  s_min = (int*)(smem + SMIN);
    int*  s_cnt = (int*)(smem + SCNT);

    const int tid  = threadIdx.x;
    const int lane = tid & 31;
    const int wid  = tid >> 5;
    const int mg   = wid >> 2;
    const int ng   = wid & 3;
    const int bid  = blockIdx.x;
    const int n0   = bid * 128;
    const int b    = n0 >> 11;
    const int t0   = n0 & 2047;

    if (tid < 128) s_min[tid] = 0x7f800000;
    if (tid == 0)  s_cnt[0] = 0;

    {
        const float* zb = z + (size_t)b * (Dd * Tt) + t0;
        #pragma unroll
        for (int it = 0; it < 8; it++) {
            int i  = it * ATC + tid;
            int d  = i >> 5;
            int t4 = (i & 31) << 2;
            float4 v = *reinterpret_cast<const float4*>(zb + (size_t)d * Tt + t4);
            float vv[4] = {v.x, v.y, v.z, v.w};
            #pragma unroll
            for (int j = 0; j < 4; j++)
                *(__nv_bfloat16*)(smem + ZHI + (t4 + j) * RS2 + d * 2) = __float2bfloat16(vv[j]);
        }
    }

    auto issue_e = [&](int ch) {
        const int kc = ch << 7;
        const uint32_t eb = sbase + EBUF + (uint32_t)(ch & 1) * EBUFSZ;
        const uint4* sh = g_ehi4 + (size_t)kc * 16;
        #pragma unroll
        for (int it = 0; it < 4; it++) {
            int i = it * ATC + tid;
            int c = i >> 4, q = i & 15;
            CP_ASYNC16(eb + (uint32_t)(c * RS2 + q * 16), sh + i);
        }
        CP_COMMIT();
    };

    const uint32_t aoffh = sbase + ZHI
        + (uint32_t)(mg * 32 + (lane & 15)) * RS2 + (uint32_t)((lane >> 4) * 16);
    const int lg = lane >> 3, lr = lane & 7;
    const uint32_t boffR =
        (uint32_t)(ng * 32 + lr + ((lg >= 2) ? 8 : 0)) * RS2 + (uint32_t)((lg & 1) ? 16 : 0);

    int rowix[4];
    #pragma unroll
    for (int mt = 0; mt < 2; mt++)
        #pragma unroll
        for (int h = 0; h < 2; h++)
            rowix[mt * 2 + h] = mg * 32 + mt * 16 + (lane >> 2) + 8 * h;

    issue_e(0);

    for (int ch = 0; ch < 16; ch++) {
        const int kc = ch << 7;
        if (ch < 15) { issue_e(ch + 1); CP_WAIT1(); }
        else         { CP_WAIT0(); }
        __syncthreads();

        const uint32_t bh = sbase + EBUF + (uint32_t)(ch & 1) * EBUFSZ + boffR;

        float acc[2][4][4];
        #pragma unroll
        for (int mt = 0; mt < 2; mt++)
            #pragma unroll
            for (int nt = 0; nt < 4; nt++)
                #pragma unroll
                for (int r = 0; r < 4; r++) acc[mt][nt][r] = 0.f;

        #pragma unroll
        for (int kk = 0; kk < 8; kk++) {
            uint32_t bfh[4][2];
            #pragma unroll
            for (int p = 0; p < 2; p++)
                LDSM4(bfh[2 * p][0], bfh[2 * p][1], bfh[2 * p + 1][0], bfh[2 * p + 1][1],
                      bh + p * (16 * RS2) + kk * 32);
            #pragma unroll
            for (int mt = 0; mt < 2; mt++) {
                uint32_t ah[4];
                LDSM4(ah[0], ah[1], ah[2], ah[3], aoffh + mt * (16 * RS2) + kk * 32);
                #pragma unroll
                for (int nt = 0; nt < 4; nt++)
                    HMMA(acc[mt][nt], ah, bfh[nt][0], bfh[nt][1]);
            }
        }

        // phase A: per-row-slot chunk-min -> quad shfl-min -> smem atomicMin
        float lm[4];
        #pragma unroll
        for (int r = 0; r < 4; r++) lm[r] = 3.4e38f;
        float e2v[4][2];
        #pragma unroll
        for (int nt = 0; nt < 4; nt++) {
            int cl = ng * 32 + nt * 8 + 2 * (lane & 3);
            e2v[nt][0] = __ldg(&g_en2[kc + cl]) + DOFF;
            e2v[nt][1] = __ldg(&g_en2[kc + cl + 1]) + DOFF;
            #pragma unroll
            for (int mt = 0; mt < 2; mt++)
                #pragma unroll
                for (int h = 0; h < 2; h++) {
                    int rs = mt * 2 + h;
                    float d0 = fmaf(-2.f, acc[mt][nt][2 * h + 0], e2v[nt][0]);
                    float d1 = fmaf(-2.f, acc[mt][nt][2 * h + 1], e2v[nt][1]);
                    lm[rs] = fminf(lm[rs], fminf(d0, d1));
                }
        }
        #pragma unroll
        for (int rs = 0; rs < 4; rs++) {
            float m = lm[rs];
            m = fminf(m, __shfl_xor_sync(0xffffffffu, m, 1));
            m = fminf(m, __shfl_xor_sync(0xffffffffu, m, 2));
            if ((lane & 3) == 0)
                atomicMin(&s_min[rowix[rs]], __float_as_int(m));
        }
        __syncthreads();   // REQUIRED: protects e-buffer reuse + exact thresholds

        // phase B: collect candidates within MARG of running min
        float thr[4];
        #pragma unroll
        for (int rs = 0; rs < 4; rs++)
            thr[rs] = __int_as_float(s_min[rowix[rs]]) + MARG;
        #pragma unroll
        for (int nt = 0; nt < 4; nt++) {
            int cl = ng * 32 + nt * 8 + 2 * (lane & 3);
            #pragma unroll
            for (int mt = 0; mt < 2; mt++)
                #pragma unroll
                for (int h = 0; h < 2; h++) {
                    int rs = mt * 2 + h;
                    float d0 = fmaf(-2.f, acc[mt][nt][2 * h + 0], e2v[nt][0]);
                    float d1 = fmaf(-2.f, acc[mt][nt][2 * h + 1], e2v[nt][1]);
                    if (d0 <= thr[rs]) {
                        int p = atomicAdd(s_cnt, 1);
                        if (p < CAP) g_slab[bid * CAP + p] = make_int2(rowix[rs], kc + cl);
                    }
                    if (d1 <= thr[rs]) {
                        int p = atomicAdd(s_cnt, 1);
                        if (p < CAP) g_slab[bid * CAP + p] = make_int2(rowix[rs], kc + cl + 1);
                    }
                }
        }
    }

    __syncthreads();
    if (tid == 0) g_scnt[bid] = min(s_cnt[0], CAP);
    if (s_cnt[0] > CAP && tid < 128) {
        int p = atomicAdd(&g_nff, 1);
        g_ffn[p] = n0 + tid;
    }
}

// ---------------------------------------------------------------------------
// K1b (pass 2): exact fp32 distance per candidate (SMEM-staged z tile),
// then fused full-rescan for overflow-flagged rows.
// ---------------------------------------------------------------------------
#define CRS 132
__global__ __launch_bounds__(256, 2)
void k_cand(const float* __restrict__ z, const float* __restrict__ emb) {
    __shared__ float zs[128 * CRS];
    __shared__ float wv[8];
    __shared__ int   wk[8];
    int bid = blockIdx.x;
    int tid = threadIdx.x;
    int cnt = g_scnt[bid];
    int n0 = bid * 128, b = n0 >> 11, t0 = n0 & 2047;

    if (cnt > 0) {
        const float* zb = z + (size_t)b * (Dd * Tt) + t0;
        #pragma unroll
        for (int it = 0; it < 16; it++) {
            int i  = it * 256 + tid;
            int d  = i >> 5;
            int t4 = (i & 31) << 2;
            float4 v = *reinterpret_cast<const float4*>(zb + (size_t)d * Tt + t4);
            zs[(t4 + 0) * CRS + d] = v.x;
            zs[(t4 + 1) * CRS + d] = v.y;
            zs[(t4 + 2) * CRS + d] = v.z;
            zs[(t4 + 3) * CRS + d] = v.w;
        }
    }
    __syncthreads();

    int wid = tid >> 5, lane = tid & 31;
    for (int i = wid; i < cnt; i += 8) {
        int2 e = g_slab[bid * CAP + i];
        int r = e.x, c = e.y;
        float4 ev = __ldg(&reinterpret_cast<const float4*>(emb + (size_t)c * Dd)[lane]);
        float4 zv = *reinterpret_cast<const float4*>(zs + r * CRS + 4 * lane);
        float d = zv.x * ev.x + zv.y * ev.y + zv.z * ev.z + zv.w * ev.w;
        #pragma unroll
        for (int o = 16; o > 0; o >>= 1) d += __shfl_down_sync(0xffffffffu, d, o);
        if (lane == 0) {
            float dist = g_en2[c] - 2.0f * d + DOFF;
            unsigned long long key =
                ((unsigned long long)__float_as_uint(dist) << 11) | (unsigned)c;
            atomicMin(&g_best[n0 + r], key);
        }
    }

    int nf = g_nff;
    for (int f = bid; f < nf; f += gridDim.x) {
        __syncthreads();
        int n = g_ffn[f];
        int bb = n >> 11, t = n & 2047;
        float zd[4];
        #pragma unroll
        for (int j = 0; j < 4; j++)
            zd[j] = z[(size_t)bb * (Dd * Tt) + (size_t)(lane * 4 + j) * Tt + t];
        float best = 3.4e38f; int bk = 0;
        for (int c = wid; c < Kk; c += 8) {
            float4 e = reinterpret_cast<const float4*>(emb + (size_t)c * Dd)[lane];
            float d = zd[0] * e.x + zd[1] * e.y + zd[2] * e.z + zd[3] * e.w;
            #pragma unroll
            for (int o = 16; o > 0; o >>= 1) d += __shfl_down_sync(0xffffffffu, d, o);
            if (lane == 0) {
                float s = g_en2[c] - 2.0f * d;
                if (s < best) { best = s; bk = c; }
            }
        }
        if (lane == 0) { wv[wid] = best; wk[wid] = bk; }
        __syncthreads();
        if (tid == 0) {
            float bv = wv[0]; int bbk = wk[0];
            #pragma unroll
            for (int w = 1; w < 8; w++)
                if (wv[w] < bv || (wv[w] == bv && wk[w] < bbk)) { bv = wv[w]; bbk = wk[w]; }
            unsigned long long key =
                ((unsigned long long)__float_as_uint(bv + DOFF) << 11) | (unsigned)bbk;
            atomicMin(&g_best[n], key);
        }
    }
}

// ---------------------------------------------------------------------------
// K3 (R15 shape): winner unpack + histogram + z_vq_out gather + z_enc_loss
//     + VECTOR red.v4 scatter into aligned g_sum.
// ---------------------------------------------------------------------------
__global__ __launch_bounds__(256)
void k_output(const float* __restrict__ z, const float* __restrict__ emb,
              float* __restrict__ out_zvq) {
    __shared__ int    kk[32];
    __shared__ float  er[32 * 133];
    __shared__ double red[256];
    int tx  = threadIdx.x;
    int ty  = threadIdx.y;
    int tid = ty * 32 + tx;
    int t0  = blockIdx.x * 32;
    int b   = blockIdx.y;

    if (tid < 32) {
        int k = (int)(g_best[b * Tt + t0 + tid] & 2047ull);
        kk[tid] = k;
        atomicAdd(&g_cnt[k], 1);
    }
    __syncthreads();
    for (int i = tid; i < 32 * 32; i += 256) {
        int r  = i >> 5;
        int d4 = (i & 31) << 2;
        float4 v = *reinterpret_cast<const float4*>(emb + (size_t)kk[r] * Dd + d4);
        er[r * 133 + d4 + 0] = v.x;
        er[r * 133 + d4 + 1] = v.y;
        er[r * 133 + d4 + 2] = v.z;
        er[r * 133 + d4 + 3] = v.w;
    }
    __syncthreads();

    size_t base = (size_t)b * Dd * Tt + t0 + tx;
    float* gs = (float*)g_sum4 + kk[tx] * Dd;

    float zv[16], vv[16];
    #pragma unroll
    for (int j = 0; j < 4; j++) {
        int d0 = ty * 16 + j * 4;
        #pragma unroll
        for (int q = 0; q < 4; q++) {
            int d = d0 + q;
            zv[j * 4 + q] = __ldg(z + base + (size_t)d * Tt);
            vv[j * 4 + q] = er[tx * 133 + d];
        }
    }
    float l0 = 0.f, l1 = 0.f, l2 = 0.f, l3 = 0.f;
    #pragma unroll
    for (int j = 0; j < 4; j++) {
        int d0 = ty * 16 + j * 4;
        #pragma unroll
        for (int q = 0; q < 4; q++) {
            int d = d0 + q;
            __stcs(out_zvq + base + (size_t)d * Tt, vv[j * 4 + q]);
        }
        REDV4(gs + d0,
              __fmul_rn(C1f, zv[j * 4 + 0]), __fmul_rn(C1f, zv[j * 4 + 1]),
              __fmul_rn(C1f, zv[j * 4 + 2]), __fmul_rn(C1f, zv[j * 4 + 3]));
        float d0f = vv[j * 4 + 0] - zv[j * 4 + 0];
        float d1f = vv[j * 4 + 1] - zv[j * 4 + 1];
        float d2f = vv[j * 4 + 2] - zv[j * 4 + 2];
        float d3f = vv[j * 4 + 3] - zv[j * 4 + 3];
        l0 += d0f * d0f; l1 += d1f * d1f; l2 += d2f * d2f; l3 += d3f * d3f;
    }
    red[tid] = (double)((l0 + l1) + (l2 + l3));
    __syncthreads();
    for (int s = 128; s > 0; s >>= 1) {
        if (tid < s) red[tid] += red[tid + s];
        __syncthreads();
    }
    if (tid == 0) atomicAdd(&g_loss, red[0]);
}

// ---------------------------------------------------------------------------
// K4: vectorized — float4 loads, 4 elems/thread; emb_sum_n copy, emb_new,
// emb_elem_n, dk partials; last block writes scalar outputs.
// ---------------------------------------------------------------------------
#define NEWBLK (Kk * Dd / 4 / 256)   // 256 blocks
__global__ __launch_bounds__(256)
void k_new(const float* __restrict__ emb, const float* __restrict__ emb_elem,
           const float* __restrict__ emb_rand,
           float* __restrict__ out_sum,
           float* __restrict__ out_new, float* __restrict__ out_elem,
           float* __restrict__ out) {
    __shared__ double red[256];
    __shared__ bool last;
    int tid = threadIdx.x;
    int i4 = blockIdx.x * 256 + tid;     // float4 index over Kk*Dd/4
    int i  = i4 << 2;
    int k  = i >> 7;

    float4 sv = g_sum4[i4];
    float4 em = *reinterpret_cast<const float4*>(emb + i);
    float4 er = *reinterpret_cast<const float4*>(emb_rand + i);
    float ee = __fadd_rn(__fmul_rn(MUf, emb_elem[k]), __fmul_rn(C1f, (float)g_cnt[k]));
    bool use = (ee >= 1.0f);
    float v0 = use ? (sv.x / ee) : er.x;
    float v1 = use ? (sv.y / ee) : er.y;
    float v2 = use ? (sv.z / ee) : er.z;
    float v3 = use ? (sv.w / ee) : er.w;
    out_sum[i + 0] = sv.x; out_sum[i + 1] = sv.y;
    out_sum[i + 2] = sv.z; out_sum[i + 3] = sv.w;
    out_new[i + 0] = v0;   out_new[i + 1] = v1;
    out_new[i + 2] = v2;   out_new[i + 3] = v3;
    if ((i & 127) == 0) out_elem[k] = ee;

    float a0 = v0 - em.x, a1 = v1 - em.y, a2 = v2 - em.z, a3 = v3 - em.w;
    red[tid] = (double)((a0 * a0 + a1 * a1) + (a2 * a2 + a3 * a3));
    __syncthreads();
    for (int s = 128; s > 0; s >>= 1) {
        if (tid < s) red[tid] += red[tid + s];
        __syncthreads();
    }
    if (tid == 0) {
        atomicAdd(&g_dk2, red[0]);
        __threadfence();
        last = (atomicAdd(&g_done, 1) == NEWBLK - 1);
    }
    __syncthreads();
    if (last) {
        double s = 0.0;
        for (int c = tid; c < Kk; c += 256) {
            float p = (float)g_cnt[c] * (1.0f / 65536.0f);
            s += (double)(p * logf(p + 1e-8f));
        }
        red[tid] = s;
        __syncthreads();
        for (int st = 128; st > 0; st >>= 1) {
            if (tid < st) red[tid] += red[tid + st];
            __syncthreads();
        }
        if (tid == 0) {
            out[OFF_LOSS] = (float)g_loss;
            out[OFF_ENT]  = expf(-(float)red[0]);
            out[OFF_DK]   = (float)(sqrt(g_dk2) / 512.0);
        }
    }
}

// ---------------------------------------------------------------------------
extern "C" void kernel_launch(void* const* d_in, const int* in_sizes, int n_in,
                              void* d_out, int out_size) {
    const float* z        = (const float*)d_in[0];
    const float* emb      = (const float*)d_in[1];
    const float* emb_sum  = (const float*)d_in[2];
    const float* emb_elem = (const float*)d_in[3];
    const float* emb_rand = (const float*)d_in[4];
    float* out      = (float*)d_out;
    float* out_zvq  = out + OFF_ZVQ;
    float* out_new  = out + OFF_EMBNEW;
    float* out_sum  = out + OFF_EMBSUM;
    float* out_elem = out + OFF_ELEM;

    cudaFuncSetAttribute(k_assign_mma, cudaFuncAttributeMaxDynamicSharedMemorySize, ASM_SMEM);

    k_prep<<<Kk, 32>>>(emb, emb_sum);
    k_assign_mma<<<Nn / 128, ATC, ASM_SMEM>>>(z);
    k_cand<<<512, 256>>>(z, emb);
    k_output<<<dim3(Tt / 32, Bz), dim3(32, 8)>>>(z, emb, out_zvq);
    k_new<<<NEWBLK, 256>>>(emb, emb_elem, emb_rand, out_sum, out_new, out_elem, out);
}

// round 17
// speedup vs baseline: 1.0215x; 1.0215x over previous
#include <cuda_runtime.h>
#include <cuda_bf16.h>
#include <math.h>
#include <cstdint>

// Problem constants
#define Bz 32
#define Dd 128
#define Tt 2048
#define Kk 2048
#define Nn 65536   // Bz*Tt

// Output layout (concatenated reference tuple, all float32)
#define OFF_ZVQ     0
#define OFF_LOSS    8388608
#define OFF_EMBNEW  8388609
#define OFF_EMBSUM  8650753
#define OFF_ELEM    8912897
#define OFF_ENT     8914945
#define OFF_DK      8914946

#define MARG 0.40f
#define DOFF 1024.0f
#define CAP  3072

__device__ __constant__ float MUf  = 0.99f;
__device__ __constant__ float C1f  = (float)(1.0 - 0.99);

// Scratch (device globals; no allocation allowed)
__device__ int    g_cnt[Kk];
__device__ float  g_en2[Kk];
__device__ double g_loss;
__device__ double g_dk2;
__device__ uint4  g_ehi4[Kk * 16];            // [code][128 bf16] hi
__device__ unsigned long long g_best[Nn];     // packed (distbits<<11 | code)
__device__ int2   g_slab[512 * CAP];          // candidate (row, code) per pass1-CTA
__device__ int    g_done;
__device__ float4 g_sum4[Kk * Dd / 4];        // 16B-aligned EMA-sum accumulator

// ---------------------------------------------------------------------------
// Generic-PTX helpers (valid on compute_103)
// ---------------------------------------------------------------------------
__device__ __forceinline__ uint32_t smem_to_u32(const void* p) {
    uint32_t a;
    asm("{ .reg .u64 t; cvta.to.shared.u64 t, %1; cvt.u32.u64 %0, t; }" : "=r"(a) : "l"(p));
    return a;
}
#define LDSM4(r0, r1, r2, r3, addr) \
    asm volatile("ldmatrix.sync.aligned.m8n8.x4.shared.b16 {%0,%1,%2,%3}, [%4];" \
                 : "=r"(r0), "=r"(r1), "=r"(r2), "=r"(r3) : "r"(addr))
#define HMMA(c, a, b0, b1) \
    asm volatile("mma.sync.aligned.m16n8k16.row.col.f32.bf16.bf16.f32 " \
                 "{%0,%1,%2,%3}, {%4,%5,%6,%7}, {%8,%9}, {%0,%1,%2,%3};" \
                 : "+f"((c)[0]), "+f"((c)[1]), "+f"((c)[2]), "+f"((c)[3]) \
                 : "r"((a)[0]), "r"((a)[1]), "r"((a)[2]), "r"((a)[3]), "r"(b0), "r"(b1))
#define CP_ASYNC16(dst, src) \
    asm volatile("cp.async.cg.shared.global [%0], [%1], 16;" :: "r"(dst), "l"(src))
#define CP_COMMIT() asm volatile("cp.async.commit_group;" ::: "memory")
#define CP_WAIT1()  asm volatile("cp.async.wait_group 1;" ::: "memory")
#define CP_WAIT0()  asm volatile("cp.async.wait_group 0;" ::: "memory")
#define REDV4(ptr, a, b, c, d) \
    asm volatile("red.global.add.v4.f32 [%0], {%1, %2, %3, %4};" \
                 :: "l"(ptr), "f"(a), "f"(b), "f"(c), "f"(d) : "memory")

// ---------------------------------------------------------------------------
// K0: fused prep — one warp per code. float4 reads, packed bf16x2 stores.
// ---------------------------------------------------------------------------
__global__ __launch_bounds__(32)
void k_prep(const float* __restrict__ emb, const float* __restrict__ emb_sum) {
    int k = blockIdx.x, lane = threadIdx.x;
    int i4 = k * 32 + lane;
    float4 e = reinterpret_cast<const float4*>(emb)[i4];
    float4 s4 = reinterpret_cast<const float4*>(emb_sum)[i4];

    __nv_bfloat162 h01 = {__float2bfloat16(e.x), __float2bfloat16(e.y)};
    __nv_bfloat162 h23 = {__float2bfloat16(e.z), __float2bfloat16(e.w)};
    uint2 hp;
    hp.x = *reinterpret_cast<uint32_t*>(&h01);
    hp.y = *reinterpret_cast<uint32_t*>(&h23);
    reinterpret_cast<uint2*>(g_ehi4)[i4] = hp;

    g_sum4[i4] = make_float4(__fmul_rn(MUf, s4.x), __fmul_rn(MUf, s4.y),
                             __fmul_rn(MUf, s4.z), __fmul_rn(MUf, s4.w));

    float sq = e.x * e.x + e.y * e.y + e.z * e.z + e.w * e.w;
    #pragma unroll
    for (int o = 16; o > 0; o >>= 1) sq += __shfl_down_sync(0xffffffffu, sq, o);
    if (lane == 0) { g_en2[k] = sq; g_cnt[k] = 0; }
    g_best[k * 32 + lane] = ~0ull;
    if (k == 0 && lane == 1) { g_loss = 0.0; g_dk2 = 0.0; g_done = 0; }
}

// ---------------------------------------------------------------------------
// K1: mma.sync bf16 single-term filter + FUSED exact-fp32 candidate pass.
// Chunk loop identical to R15 (proven barriers). Tail: re-stage fp32 z tile
// into the dead e-buffer area, verify this CTA's own slab (CTA-local by
// construction), atomicMin into g_best. Overflow => in-CTA full rescan.
// ---------------------------------------------------------------------------
#define ATC 512
#define RS2 272
#define ZHI 0
#define EBUF 34816
#define EBUFSZ 34816
#define SMIN (EBUF + 2 * EBUFSZ)
#define SCNT (SMIN + 512)
#define ASM_SMEM (SCNT + 16)
#define CRS 132

__global__ __launch_bounds__(ATC, 2)
void k_assign_mma(const float* __restrict__ z, const float* __restrict__ emb)
{
    extern __shared__ char smem[];
    const uint32_t sbase = smem_to_u32(smem);
    int*  s_min = (int*)(smem + SMIN);
    int*  s_cnt = (int*)(smem + SCNT);

    const int tid  = threadIdx.x;
    const int lane = tid & 31;
    const int wid  = tid >> 5;
    const int mg   = wid >> 2;
    const int ng   = wid & 3;
    const int bid  = blockIdx.x;
    const int n0   = bid * 128;
    const int b    = n0 >> 11;
    const int t0   = n0 & 2047;

    if (tid < 128) s_min[tid] = 0x7f800000;
    if (tid == 0)  s_cnt[0] = 0;

    {
        const float* zb = z + (size_t)b * (Dd * Tt) + t0;
        #pragma unroll
        for (int it = 0; it < 8; it++) {
            int i  = it * ATC + tid;
            int d  = i >> 5;
            int t4 = (i & 31) << 2;
            float4 v = *reinterpret_cast<const float4*>(zb + (size_t)d * Tt + t4);
            float vv[4] = {v.x, v.y, v.z, v.w};
            #pragma unroll
            for (int j = 0; j < 4; j++)
                *(__nv_bfloat16*)(smem + ZHI + (t4 + j) * RS2 + d * 2) = __float2bfloat16(vv[j]);
        }
    }

    auto issue_e = [&](int ch) {
        const int kc = ch << 7;
        const uint32_t eb = sbase + EBUF + (uint32_t)(ch & 1) * EBUFSZ;
        const uint4* sh = g_ehi4 + (size_t)kc * 16;
        #pragma unroll
        for (int it = 0; it < 4; it++) {
            int i = it * ATC + tid;
            int c = i >> 4, q = i & 15;
            CP_ASYNC16(eb + (uint32_t)(c * RS2 + q * 16), sh + i);
        }
        CP_COMMIT();
    };

    const uint32_t aoffh = sbase + ZHI
        + (uint32_t)(mg * 32 + (lane & 15)) * RS2 + (uint32_t)((lane >> 4) * 16);
    const int lg = lane >> 3, lr = lane & 7;
    const uint32_t boffR =
        (uint32_t)(ng * 32 + lr + ((lg >= 2) ? 8 : 0)) * RS2 + (uint32_t)((lg & 1) ? 16 : 0);

    int rowix[4];
    #pragma unroll
    for (int mt = 0; mt < 2; mt++)
        #pragma unroll
        for (int h = 0; h < 2; h++)
            rowix[mt * 2 + h] = mg * 32 + mt * 16 + (lane >> 2) + 8 * h;

    issue_e(0);

    for (int ch = 0; ch < 16; ch++) {
        const int kc = ch << 7;
        if (ch < 15) { issue_e(ch + 1); CP_WAIT1(); }
        else         { CP_WAIT0(); }
        __syncthreads();

        const uint32_t bh = sbase + EBUF + (uint32_t)(ch & 1) * EBUFSZ + boffR;

        float acc[2][4][4];
        #pragma unroll
        for (int mt = 0; mt < 2; mt++)
            #pragma unroll
            for (int nt = 0; nt < 4; nt++)
                #pragma unroll
                for (int r = 0; r < 4; r++) acc[mt][nt][r] = 0.f;

        #pragma unroll
        for (int kk = 0; kk < 8; kk++) {
            uint32_t bfh[4][2];
            #pragma unroll
            for (int p = 0; p < 2; p++)
                LDSM4(bfh[2 * p][0], bfh[2 * p][1], bfh[2 * p + 1][0], bfh[2 * p + 1][1],
                      bh + p * (16 * RS2) + kk * 32);
            #pragma unroll
            for (int mt = 0; mt < 2; mt++) {
                uint32_t ah[4];
                LDSM4(ah[0], ah[1], ah[2], ah[3], aoffh + mt * (16 * RS2) + kk * 32);
                #pragma unroll
                for (int nt = 0; nt < 4; nt++)
                    HMMA(acc[mt][nt], ah, bfh[nt][0], bfh[nt][1]);
            }
        }

        // phase A: per-row-slot chunk-min -> quad shfl-min -> smem atomicMin
        float lm[4];
        #pragma unroll
        for (int r = 0; r < 4; r++) lm[r] = 3.4e38f;
        float e2v[4][2];
        #pragma unroll
        for (int nt = 0; nt < 4; nt++) {
            int cl = ng * 32 + nt * 8 + 2 * (lane & 3);
            e2v[nt][0] = __ldg(&g_en2[kc + cl]) + DOFF;
            e2v[nt][1] = __ldg(&g_en2[kc + cl + 1]) + DOFF;
            #pragma unroll
            for (int mt = 0; mt < 2; mt++)
                #pragma unroll
                for (int h = 0; h < 2; h++) {
                    int rs = mt * 2 + h;
                    float d0 = fmaf(-2.f, acc[mt][nt][2 * h + 0], e2v[nt][0]);
                    float d1 = fmaf(-2.f, acc[mt][nt][2 * h + 1], e2v[nt][1]);
                    lm[rs] = fminf(lm[rs], fminf(d0, d1));
                }
        }
        #pragma unroll
        for (int rs = 0; rs < 4; rs++) {
            float m = lm[rs];
            m = fminf(m, __shfl_xor_sync(0xffffffffu, m, 1));
            m = fminf(m, __shfl_xor_sync(0xffffffffu, m, 2));
            if ((lane & 3) == 0)
                atomicMin(&s_min[rowix[rs]], __float_as_int(m));
        }
        __syncthreads();   // REQUIRED: protects e-buffer reuse + exact thresholds

        // phase B: collect candidates within MARG of running min
        float thr[4];
        #pragma unroll
        for (int rs = 0; rs < 4; rs++)
            thr[rs] = __int_as_float(s_min[rowix[rs]]) + MARG;
        #pragma unroll
        for (int nt = 0; nt < 4; nt++) {
            int cl = ng * 32 + nt * 8 + 2 * (lane & 3);
            #pragma unroll
            for (int mt = 0; mt < 2; mt++)
                #pragma unroll
                for (int h = 0; h < 2; h++) {
                    int rs = mt * 2 + h;
                    float d0 = fmaf(-2.f, acc[mt][nt][2 * h + 0], e2v[nt][0]);
                    float d1 = fmaf(-2.f, acc[mt][nt][2 * h + 1], e2v[nt][1]);
                    if (d0 <= thr[rs]) {
                        int p = atomicAdd(s_cnt, 1);
                        if (p < CAP) g_slab[bid * CAP + p] = make_int2(rowix[rs], kc + cl);
                    }
                    if (d1 <= thr[rs]) {
                        int p = atomicAdd(s_cnt, 1);
                        if (p < CAP) g_slab[bid * CAP + p] = make_int2(rowix[rs], kc + cl + 1);
                    }
                }
        }
    }

    // ================= FUSED candidate verification =================
    __syncthreads();                     // slab writes visible block-wide
    const int cnt = s_cnt[0];

    // stage fp32 z tile into the (now dead) e-buffer region: zs[t][d] str 132
    float* zs = (float*)(smem + EBUF);   // 67584 B <= 69632 B
    {
        const float* zb = z + (size_t)b * (Dd * Tt) + t0;
        #pragma unroll
        for (int it = 0; it < 8; it++) {
            int i  = it * ATC + tid;
            int d  = i >> 5;
            int t4 = (i & 31) << 2;
            float4 v = *reinterpret_cast<const float4*>(zb + (size_t)d * Tt + t4);
            zs[(t4 + 0) * CRS + d] = v.x;
            zs[(t4 + 1) * CRS + d] = v.y;
            zs[(t4 + 2) * CRS + d] = v.z;
            zs[(t4 + 3) * CRS + d] = v.w;
        }
    }
    __syncthreads();

    if (cnt <= CAP) {
        // exact fp32 distance per candidate; 16 warps
        for (int i = wid; i < cnt; i += 16) {
            int2 e = g_slab[bid * CAP + i];
            int r = e.x, c = e.y;
            float4 ev = __ldg(&reinterpret_cast<const float4*>(emb + (size_t)c * Dd)[lane]);
            float4 zv = *reinterpret_cast<const float4*>(zs + r * CRS + 4 * lane);
            float d = zv.x * ev.x + zv.y * ev.y + zv.z * ev.z + zv.w * ev.w;
            #pragma unroll
            for (int o = 16; o > 0; o >>= 1) d += __shfl_down_sync(0xffffffffu, d, o);
            if (lane == 0) {
                float dist = g_en2[c] - 2.0f * d + DOFF;
                unsigned long long key =
                    ((unsigned long long)__float_as_uint(dist) << 11) | (unsigned)c;
                atomicMin(&g_best[n0 + r], key);
            }
        }
    } else {
        // overflow (never expected): full fp32 rescan of this CTA's 128 rows
        for (int r = wid; r < 128; r += 16) {
            float4 zv = *reinterpret_cast<const float4*>(zs + r * CRS + 4 * lane);
            float best = 3.4e38f; int bk = 0;
            for (int c = 0; c < Kk; c++) {
                float4 ev = __ldg(&reinterpret_cast<const float4*>(emb + (size_t)c * Dd)[lane]);
                float d = zv.x * ev.x + zv.y * ev.y + zv.z * ev.z + zv.w * ev.w;
                #pragma unroll
                for (int o = 16; o > 0; o >>= 1) d += __shfl_down_sync(0xffffffffu, d, o);
                d = __shfl_sync(0xffffffffu, d, 0);
                float s = g_en2[c] - 2.0f * d;
                if (s < best) { best = s; bk = c; }
            }
            if (lane == 0)
                g_best[n0 + r] = ((unsigned long long)__float_as_uint(best + DOFF) << 11)
                                 | (unsigned)bk;
        }
    }
}

// ---------------------------------------------------------------------------
// K3 (R15 shape): winner unpack + histogram + z_vq_out gather + z_enc_loss
//     + VECTOR red.v4 scatter into aligned g_sum.
// ---------------------------------------------------------------------------
__global__ __launch_bounds__(256)
void k_output(const float* __restrict__ z, const float* __restrict__ emb,
              float* __restrict__ out_zvq) {
    __shared__ int    kk[32];
    __shared__ float  er[32 * 133];
    __shared__ double red[256];
    int tx  = threadIdx.x;
    int ty  = threadIdx.y;
    int tid = ty * 32 + tx;
    int t0  = blockIdx.x * 32;
    int b   = blockIdx.y;

    if (tid < 32) {
        int k = (int)(g_best[b * Tt + t0 + tid] & 2047ull);
        kk[tid] = k;
        atomicAdd(&g_cnt[k], 1);
    }
    __syncthreads();
    for (int i = tid; i < 32 * 32; i += 256) {
        int r  = i >> 5;
        int d4 = (i & 31) << 2;
        float4 v = *reinterpret_cast<const float4*>(emb + (size_t)kk[r] * Dd + d4);
        er[r * 133 + d4 + 0] = v.x;
        er[r * 133 + d4 + 1] = v.y;
        er[r * 133 + d4 + 2] = v.z;
        er[r * 133 + d4 + 3] = v.w;
    }
    __syncthreads();

    size_t base = (size_t)b * Dd * Tt + t0 + tx;
    float* gs = (float*)g_sum4 + kk[tx] * Dd;

    float zv[16], vv[16];
    #pragma unroll
    for (int j = 0; j < 4; j++) {
        int d0 = ty * 16 + j * 4;
        #pragma unroll
        for (int q = 0; q < 4; q++) {
            int d = d0 + q;
            zv[j * 4 + q] = __ldg(z + base + (size_t)d * Tt);
            vv[j * 4 + q] = er[tx * 133 + d];
        }
    }
    float l0 = 0.f, l1 = 0.f, l2 = 0.f, l3 = 0.f;
    #pragma unroll
    for (int j = 0; j < 4; j++) {
        int d0 = ty * 16 + j * 4;
        #pragma unroll
        for (int q = 0; q < 4; q++) {
            int d = d0 + q;
            __stcs(out_zvq + base + (size_t)d * Tt, vv[j * 4 + q]);
        }
        REDV4(gs + d0,
              __fmul_rn(C1f, zv[j * 4 + 0]), __fmul_rn(C1f, zv[j * 4 + 1]),
              __fmul_rn(C1f, zv[j * 4 + 2]), __fmul_rn(C1f, zv[j * 4 + 3]));
        float d0f = vv[j * 4 + 0] - zv[j * 4 + 0];
        float d1f = vv[j * 4 + 1] - zv[j * 4 + 1];
        float d2f = vv[j * 4 + 2] - zv[j * 4 + 2];
        float d3f = vv[j * 4 + 3] - zv[j * 4 + 3];
        l0 += d0f * d0f; l1 += d1f * d1f; l2 += d2f * d2f; l3 += d3f * d3f;
    }
    red[tid] = (double)((l0 + l1) + (l2 + l3));
    __syncthreads();
    for (int s = 128; s > 0; s >>= 1) {
        if (tid < s) red[tid] += red[tid + s];
        __syncthreads();
    }
    if (tid == 0) atomicAdd(&g_loss, red[0]);
}

// ---------------------------------------------------------------------------
// K4: vectorized — float4 loads, 4 elems/thread; emb_sum_n copy, emb_new,
// emb_elem_n, dk partials; last block writes scalar outputs.
// ---------------------------------------------------------------------------
#define NEWBLK (Kk * Dd / 4 / 256)   // 256 blocks
__global__ __launch_bounds__(256)
void k_new(const float* __restrict__ emb, const float* __restrict__ emb_elem,
           const float* __restrict__ emb_rand,
           float* __restrict__ out_sum,
           float* __restrict__ out_new, float* __restrict__ out_elem,
           float* __restrict__ out) {
    __shared__ double red[256];
    __shared__ bool last;
    int tid = threadIdx.x;
    int i4 = blockIdx.x * 256 + tid;
    int i  = i4 << 2;
    int k  = i >> 7;

    float4 sv = g_sum4[i4];
    float4 em = *reinterpret_cast<const float4*>(emb + i);
    float4 er = *reinterpret_cast<const float4*>(emb_rand + i);
    float ee = __fadd_rn(__fmul_rn(MUf, emb_elem[k]), __fmul_rn(C1f, (float)g_cnt[k]));
    bool use = (ee >= 1.0f);
    float v0 = use ? (sv.x / ee) : er.x;
    float v1 = use ? (sv.y / ee) : er.y;
    float v2 = use ? (sv.z / ee) : er.z;
    float v3 = use ? (sv.w / ee) : er.w;
    out_sum[i + 0] = sv.x; out_sum[i + 1] = sv.y;
    out_sum[i + 2] = sv.z; out_sum[i + 3] = sv.w;
    out_new[i + 0] = v0;   out_new[i + 1] = v1;
    out_new[i + 2] = v2;   out_new[i + 3] = v3;
    if ((i & 127) == 0) out_elem[k] = ee;

    float a0 = v0 - em.x, a1 = v1 - em.y, a2 = v2 - em.z, a3 = v3 - em.w;
    red[tid] = (double)((a0 * a0 + a1 * a1) + (a2 * a2 + a3 * a3));
    __syncthreads();
    for (int s = 128; s > 0; s >>= 1) {
        if (tid < s) red[tid] += red[tid + s];
        __syncthreads();
    }
    if (tid == 0) {
        atomicAdd(&g_dk2, red[0]);
        __threadfence();
        last = (atomicAdd(&g_done, 1) == NEWBLK - 1);
    }
    __syncthreads();
    if (last) {
        double s = 0.0;
        for (int c = tid; c < Kk; c += 256) {
            float p = (float)g_cnt[c] * (1.0f / 65536.0f);
            s += (double)(p * logf(p + 1e-8f));
        }
        red[tid] = s;
        __syncthreads();
        for (int st = 128; st > 0; st >>= 1) {
            if (tid < st) red[tid] += red[tid + st];
            __syncthreads();
        }
        if (tid == 0) {
            out[OFF_LOSS] = (float)g_loss;
            out[OFF_ENT]  = expf(-(float)red[0]);
            out[OFF_DK]   = (float)(sqrt(g_dk2) / 512.0);
        }
    }
}

// ---------------------------------------------------------------------------
extern "C" void kernel_launch(void* const* d_in, const int* in_sizes, int n_in,
                              void* d_out, int out_size) {
    const float* z        = (const float*)d_in[0];
    const float* emb      = (const float*)d_in[1];
    const float* emb_sum  = (const float*)d_in[2];
    const float* emb_elem = (const float*)d_in[3];
    const float* emb_rand = (const float*)d_in[4];
    float* out      = (float*)d_out;
    float* out_zvq  = out + OFF_ZVQ;
    float* out_new  = out + OFF_EMBNEW;
    float* out_sum  = out + OFF_EMBSUM;
    float* out_elem = out + OFF_ELEM;

    cudaFuncSetAttribute(k_assign_mma, cudaFuncAttributeMaxDynamicSharedMemorySize, ASM_SMEM);

    k_prep<<<Kk, 32>>>(emb, emb_sum);
    k_assign_mma<<<Nn / 128, ATC, ASM_SMEM>>>(z, emb);
    k_output<<<dim3(Tt / 32, Bz), dim3(32, 8)>>>(z, emb, out_zvq);
    k_new<<<NEWBLK, 256>>>(emb, emb_elem, emb_rand, out_sum, out_new, out_elem, out);
}